// round 2
// baseline (speedup 1.0000x reference)
#include <cuda_runtime.h>
#include <math.h>

#define Bn    4
#define Sn    2048
#define Dn    1024
#define Hn    8
#define LRn   512
#define LRHn  64
#define SHDn  128
#define EXPn  2
#define Kn    4
#define CONVn 1042
#define NPROJ 1554
#define BSn   8192   // B*S

// ---------------- scratch (device globals; no runtime allocation) ----------------
__device__ float g_proj[BSn * NPROJ];   // ~51 MB  : x @ w_in^T
__device__ float g_y[BSn * CONVn];      // ~34 MB  : conv+silu output
__device__ float g_xv[BSn * 1024];      // ~34 MB  : [B,S,H,128]
__device__ float g_fv[BSn * 1024];      // ~34 MB
__device__ float g_scan[BSn * 1024];    // ~34 MB  : residual + h*Cg
__device__ float g_v[BSn * LRn];        // ~17 MB  : normalized gated u
__device__ float g_rin[BSn * Hn];
__device__ float g_cg[BSn * Hn];
__device__ float g_sw[3 * Hn * SHDn * SHDn];  // normalized state_w

// ---------------- helpers ----------------
__device__ __forceinline__ float sigmoidf_(float x) {
    return __fdividef(1.f, 1.f + __expf(-x));
}
__device__ __forceinline__ float tanhf_(float x) {
    float t = __expf(-2.f * fabsf(x));
    float r = __fdividef(1.f - t, 1.f + t);
    return copysignf(r, x);
}
__device__ __forceinline__ float blk_sum256(float v, float* sbuf /*>=8 floats*/) {
    int lane = threadIdx.x & 31, wid = threadIdx.x >> 5;
#pragma unroll
    for (int off = 16; off; off >>= 1) v += __shfl_xor_sync(0xffffffffu, v, off);
    if (lane == 0) sbuf[wid] = v;
    __syncthreads();
    float tot = 0.f;
#pragma unroll
    for (int i = 0; i < 8; i++) tot += sbuf[i];
    __syncthreads();
    return tot;
}
__device__ __forceinline__ void cp_async16(void* smem, const void* gmem) {
    unsigned s = (unsigned)__cvta_generic_to_shared(smem);
    asm volatile("cp.async.cg.shared.global [%0], [%1], 16;\n" ::"r"(s), "l"(gmem));
}

// ---------------- K1/K6: C[M,N] = A[M,K] @ B[N,K]^T (fp32, 128x128x8 tiles) ----------------
__global__ __launch_bounds__(256) void sgemm_nt(const float* __restrict__ A,
                                                const float* __restrict__ Bm,
                                                float* __restrict__ C,
                                                int M, int N, int Kd) {
    __shared__ float As[8][128];
    __shared__ float Bs[8][128];
    int tid = threadIdx.x;
    int m0 = blockIdx.y * 128, n0 = blockIdx.x * 128;
    int tx = tid & 15, ty = tid >> 4;
    int lrow = tid >> 1, lcol = (tid & 1) * 4;

    float acc[8][8];
#pragma unroll
    for (int i = 0; i < 8; i++)
#pragma unroll
        for (int j = 0; j < 8; j++) acc[i][j] = 0.f;

    const float* Aptr = A + (size_t)(m0 + lrow) * Kd + lcol;
    const float* Bptr = Bm + (size_t)(n0 + lrow) * Kd + lcol;
    bool bvalid = (n0 + lrow) < N;

    for (int k0 = 0; k0 < Kd; k0 += 8) {
        float4 av = *(const float4*)(Aptr + k0);
        float4 bv = bvalid ? *(const float4*)(Bptr + k0) : make_float4(0.f, 0.f, 0.f, 0.f);
        __syncthreads();
        As[lcol + 0][lrow] = av.x; As[lcol + 1][lrow] = av.y;
        As[lcol + 2][lrow] = av.z; As[lcol + 3][lrow] = av.w;
        Bs[lcol + 0][lrow] = bv.x; Bs[lcol + 1][lrow] = bv.y;
        Bs[lcol + 2][lrow] = bv.z; Bs[lcol + 3][lrow] = bv.w;
        __syncthreads();
#pragma unroll
        for (int kk = 0; kk < 8; kk++) {
            float4 a0 = *(const float4*)&As[kk][ty * 8];
            float4 a1 = *(const float4*)&As[kk][ty * 8 + 4];
            float4 b0 = *(const float4*)&Bs[kk][tx * 8];
            float4 b1 = *(const float4*)&Bs[kk][tx * 8 + 4];
            float a[8] = {a0.x, a0.y, a0.z, a0.w, a1.x, a1.y, a1.z, a1.w};
            float b[8] = {b0.x, b0.y, b0.z, b0.w, b1.x, b1.y, b1.z, b1.w};
#pragma unroll
            for (int i = 0; i < 8; i++)
#pragma unroll
                for (int j = 0; j < 8; j++) acc[i][j] += a[i] * b[j];
        }
    }
#pragma unroll
    for (int i = 0; i < 8; i++) {
        int m = m0 + ty * 8 + i;
#pragma unroll
        for (int j = 0; j < 8; j++) {
            int n = n0 + tx * 8 + j;
            if (n < N) C[(size_t)m * N + n] = acc[i][j];
        }
    }
}

// ---------------- K2: causal depthwise conv (K=4) + SiLU ----------------
__global__ __launch_bounds__(256) void conv_silu_kernel(const float* __restrict__ conv_w) {
    int idx = blockIdx.x * blockDim.x + threadIdx.x;   // over BSn*CONVn
    int c = idx % CONVn;
    int row = idx / CONVn;          // b*S + s
    int s = row % Sn;
    float w0 = conv_w[c * 4 + 0], w1 = conv_w[c * 4 + 1];
    float w2 = conv_w[c * 4 + 2], w3 = conv_w[c * 4 + 3];
    float acc = w3 * g_proj[(size_t)row * NPROJ + c];
    if (s >= 1) acc += w2 * g_proj[(size_t)(row - 1) * NPROJ + c];
    if (s >= 2) acc += w1 * g_proj[(size_t)(row - 2) * NPROJ + c];
    if (s >= 3) acc += w0 * g_proj[(size_t)(row - 3) * NPROJ + c];
    g_y[(size_t)row * CONVn + c] = acc * sigmoidf_(acc);   // silu
}

// ---------------- K3b: normalize state_w per head-matrix ----------------
__global__ __launch_bounds__(256) void norm_sw_kernel(const float* __restrict__ sw_in) {
    __shared__ float sbuf[8];
    int m = blockIdx.x;  // 0..23
    const float* src = sw_in + (size_t)m * 16384;
    float ss = 0.f;
    for (int i = threadIdx.x; i < 16384; i += 256) { float v = src[i]; ss += v * v; }
    float tot = blk_sum256(ss, sbuf);
    float inv = 1.f / fmaxf(sqrtf(tot), 1e-12f);
    float* dst = g_sw + (size_t)m * 16384;
    for (int i = threadIdx.x; i < 16384; i += 256) dst[i] = src[i] * inv;
}

// ---------------- K3: norms + expand -> xv, fv, rin, cg ----------------
__global__ __launch_bounds__(256) void build_kernel(const float* __restrict__ w_in_norm,
                                                    const float* __restrict__ w_f_norm,
                                                    const float* __restrict__ w_r_norm) {
    __shared__ float sy[CONVn];
    __shared__ float sb1[8], sb2[8];
    __shared__ float srs[1];
    int row = blockIdx.x;  // b*S + s
    const float* yr = g_y + (size_t)row * CONVn;
    for (int i = threadIdx.x; i < CONVn; i += 256) sy[i] = yr[i];
    __syncthreads();

    float s1 = 0.f, s2 = 0.f;
    for (int i = threadIdx.x; i < 512; i += 256) {
        s1 += sy[i] * sy[i];
        s2 += sy[512 + i] * sy[512 + i];
    }
    float t1 = blk_sum256(s1, sb1);
    float t2 = blk_sum256(s2, sb2);
    if (threadIdx.x == 0) {
        float sr = 0.f;
#pragma unroll
        for (int h = 0; h < 8; h++) sr += sy[1024 + h] * sy[1024 + h];
        srs[0] = rsqrtf(sr * (1.f / 8.f) + 1e-6f);
    }
    float si = rsqrtf(t1 * (1.f / 512.f) + 1e-6f);
    float sf = rsqrtf(t2 * (1.f / 512.f) + 1e-6f);
    __syncthreads();

    float e0 = sy[1040], e1 = sy[1041];
    float* xv = g_xv + (size_t)row * 1024;
    float* fv = g_fv + (size_t)row * 1024;
#pragma unroll
    for (int q = 0; q < 4; q++) {
        int o = threadIdx.x + q * 256;
        int hh = o >> 7, rem = o & 127, ee = rem >> 6, dd = rem & 63;
        int ii = hh * 64 + dd;
        float ex = (ee == 0) ? e0 : e1;
        xv[o] = sy[ii] * si * w_in_norm[ii] * ex;
        fv[o] = sy[512 + ii] * sf * w_f_norm[ii] * ex;
    }
    if (threadIdx.x < 8) {
        g_rin[(size_t)row * 8 + threadIdx.x] = sy[1024 + threadIdx.x] * srs[0] * w_r_norm[threadIdx.x];
        g_cg[(size_t)row * 8 + threadIdx.x] = sy[1032 + threadIdx.x];
    }
}

// ---------------- K4: sequential recurrence, one CTA per (b,h) ----------------
__global__ __launch_bounds__(256, 1) void scan_kernel(const float* __restrict__ res_w) {
    int b = blockIdx.x >> 3, hh = blockIdx.x & 7;
    int tid = threadIdx.x;
    int e = tid & 127, half = tid >> 7;

    __shared__ __align__(16) float h_sh[128];
    __shared__ __align__(16) float rh_sh[128];
    __shared__ float f_sh[128];
    __shared__ float redR[256], redF[256], redW[256];
    __shared__ __align__(16) float xbuf[2 * 128];
    __shared__ __align__(16) float fbuf[2 * 128];
    __shared__ float rin_s[Sn], cg_s[Sn];

    // weight columns in registers: thread (e, half) holds rows [half*64, half*64+64)
    float Wreg[64], Freg[64], Rreg[64];
    {
        const float* bw = g_sw + (size_t)hh * 16384 + half * 8192 + e;
        const float* bf = g_sw + (size_t)(8 + hh) * 16384 + half * 8192 + e;
        const float* br = g_sw + (size_t)(16 + hh) * 16384 + half * 8192 + e;
#pragma unroll
        for (int i = 0; i < 64; i++) {
            Wreg[i] = bw[i * 128];
            Freg[i] = bf[i * 128];
            Rreg[i] = br[i * 128];
        }
    }
    for (int t = tid; t < Sn; t += 256) {
        rin_s[t] = g_rin[(size_t)(b * Sn + t) * 8 + hh];
        cg_s[t]  = g_cg[(size_t)(b * Sn + t) * 8 + hh];
    }
    if (tid < 128) h_sh[tid] = 0.f;
    float resw = res_w[hh];
    size_t rowbase = ((size_t)b * Sn) * 1024 + hh * 128;

    // prefetch t=0
    if (tid < 32)       cp_async16(xbuf + tid * 4, g_xv + rowbase + tid * 4);
    else if (tid < 64)  cp_async16(fbuf + (tid - 32) * 4, g_fv + rowbase + (tid - 32) * 4);
    asm volatile("cp.async.commit_group;");

    for (int t = 0; t < Sn; t++) {
        int cur = t & 1, nxt = cur ^ 1;
        if (t + 1 < Sn) {
            size_t nb = rowbase + (size_t)(t + 1) * 1024;
            if (tid < 32)      cp_async16(xbuf + nxt * 128 + tid * 4, g_xv + nb + tid * 4);
            else if (tid < 64) cp_async16(fbuf + nxt * 128 + (tid - 32) * 4, g_fv + nb + (tid - 32) * 4);
        }
        asm volatile("cp.async.commit_group;");
        asm volatile("cp.async.wait_group 1;");
        __syncthreads();  // cur buffers + h_sh ready for all threads

        float rt = rin_s[t], cgt = cg_s[t];

        // Phase A: pR = h . R[:,e], pF = h . F[:,e] over this thread's d-range
        float pR = 0.f, pF = 0.f;
        {
            const float4* h4 = (const float4*)h_sh + half * 16;
#pragma unroll
            for (int i = 0; i < 16; i++) {
                float4 hv = h4[i];
                pR += hv.x * Rreg[4 * i + 0]; pF += hv.x * Freg[4 * i + 0];
                pR += hv.y * Rreg[4 * i + 1]; pF += hv.y * Freg[4 * i + 1];
                pR += hv.z * Rreg[4 * i + 2]; pF += hv.z * Freg[4 * i + 2];
                pR += hv.w * Rreg[4 * i + 3]; pF += hv.w * Freg[4 * i + 3];
            }
        }
        redR[tid] = pR; redF[tid] = pF;
        __syncthreads();

        if (tid < 128) {
            float rv = sigmoidf_(rt + redR[tid] + redR[128 + tid]);
            rh_sh[tid] = rv * h_sh[tid];
        } else {
            int ee = tid - 128;
            float fg = sigmoidf_(fbuf[cur * 128 + ee] + redF[ee] + redF[128 + ee]);
            f_sh[ee] = fg;
        }
        __syncthreads();

        // Phase B: pW = (r*h) . W[:,e]
        float pW = 0.f;
        {
            const float4* rh4 = (const float4*)rh_sh + half * 16;
#pragma unroll
            for (int i = 0; i < 16; i++) {
                float4 hv = rh4[i];
                pW += hv.x * Wreg[4 * i + 0];
                pW += hv.y * Wreg[4 * i + 1];
                pW += hv.z * Wreg[4 * i + 2];
                pW += hv.w * Wreg[4 * i + 3];
            }
        }
        redW[tid] = pW;
        __syncthreads();

        if (tid < 128) {
            float xt = xbuf[cur * 128 + tid];
            float htl = tanhf_(xt + redW[tid] + redW[128 + tid]);
            float fg = f_sh[tid];
            float hn = fg * h_sh[tid] + (1.f - fg) * htl;
            h_sh[tid] = hn;
            g_scan[rowbase + (size_t)t * 1024 + tid] = resw * xt + hn * cgt;
        }
        __syncthreads();  // h_sh update visible before next step
    }
}

// ---------------- K5: up-proj per head + gate silu + rms -> g_v ----------------
__global__ __launch_bounds__(256) void ugate_kernel(const float* __restrict__ up_w,
                                                    const float* __restrict__ w_g_norm) {
    __shared__ float srow[1024];
    __shared__ float suw[64 * 129];   // padded to kill bank conflicts
    __shared__ float sb[8];
    int row = blockIdx.x;  // b*S + s
    int tid = threadIdx.x;

    const float* sr = g_scan + (size_t)row * 1024;
    for (int i = tid; i < 1024; i += 256) srow[i] = sr[i];
    for (int i = tid; i < 8192; i += 256) {
        int j = i >> 7, d = i & 127;
        suw[j * 129 + d] = up_w[i];
    }
    __syncthreads();

    int o0 = tid * 2, o1 = o0 + 1;
    int hhd = o0 >> 6;            // head (same for o0,o1)
    int j0 = o0 & 63, j1 = o1 & 63;
    const float* a = srow + hhd * 128;
    float acc0 = 0.f, acc1 = 0.f;
#pragma unroll 16
    for (int d = 0; d < 128; d++) {
        float av = a[d];
        acc0 += av * suw[j0 * 129 + d];
        acc1 += av * suw[j1 * 129 + d];
    }
    const float* gptr = g_proj + (size_t)row * NPROJ + CONVn;
    float gA = gptr[o0], gB = gptr[o1];
    float u0 = acc0 * (gA * sigmoidf_(gA));
    float u1 = acc1 * (gB * sigmoidf_(gB));

    float tot = blk_sum256(u0 * u0 + u1 * u1, sb);
    float scale = rsqrtf(tot * (1.f / 512.f) + 1e-6f);
    float* vout = g_v + (size_t)row * 512;
    vout[o0] = u0 * scale * w_g_norm[o0];
    vout[o1] = u1 * scale * w_g_norm[o1];
}

// ---------------- launch ----------------
extern "C" void kernel_launch(void* const* d_in, const int* in_sizes, int n_in,
                              void* d_out, int out_size) {
    const float* x         = (const float*)d_in[0];
    const float* w_in      = (const float*)d_in[1];
    const float* conv_w    = (const float*)d_in[2];
    const float* state_w   = (const float*)d_in[3];
    const float* up_w      = (const float*)d_in[4];
    const float* out_w     = (const float*)d_in[5];
    const float* res_w     = (const float*)d_in[6];
    const float* w_in_norm = (const float*)d_in[7];
    const float* w_f_norm  = (const float*)d_in[8];
    const float* w_r_norm  = (const float*)d_in[9];
    const float* w_g_norm  = (const float*)d_in[10];
    float* out = (float*)d_out;

    float* p_proj = nullptr;
    float* p_v = nullptr;
    cudaGetSymbolAddress((void**)&p_proj, g_proj);
    cudaGetSymbolAddress((void**)&p_v, g_v);

    // K1: proj = x @ w_in^T   [8192,1554,K=1024]
    sgemm_nt<<<dim3((NPROJ + 127) / 128, BSn / 128), 256>>>(x, w_in, p_proj, BSn, NPROJ, Dn);
    // K2: depthwise conv + silu
    conv_silu_kernel<<<(BSn * CONVn) / 256, 256>>>(conv_w);
    // K3b: normalize state_w
    norm_sw_kernel<<<3 * Hn, 256>>>(state_w);
    // K3: norms + expand
    build_kernel<<<BSn, 256>>>(w_in_norm, w_f_norm, w_r_norm);
    // K4: sequential scan, one CTA per (b,h)
    scan_kernel<<<Bn * Hn, 256>>>(res_w);
    // K5: up-proj + gate + rms
    ugate_kernel<<<BSn, 256>>>(up_w, w_g_norm);
    // K6: final = v @ out_w^T  [8192,1024,K=512]
    sgemm_nt<<<dim3(Dn / 128, BSn / 128), 256>>>(p_v, out_w, out, BSn, Dn, LRn);
}

// round 3
// speedup vs baseline: 1.0495x; 1.0495x over previous
#include <cuda_runtime.h>
#include <math.h>

#define Bn    4
#define Sn    2048
#define Dn    1024
#define Hn    8
#define LRn   512
#define LRHn  64
#define SHDn  128
#define EXPn  2
#define Kn    4
#define CONVn 1042
#define NPROJ 1554
#define BSn   8192   // B*S

typedef unsigned long long ull;

// ---------------- scratch (device globals; no runtime allocation) ----------------
__device__ float g_proj[BSn * NPROJ];   // ~51 MB  : x @ w_in^T
__device__ float g_y[BSn * CONVn];      // ~34 MB  : conv+silu output
__device__ float g_xv[BSn * 1024];      // ~34 MB  : [B,S,H,128]
__device__ float g_fv[BSn * 1024];      // ~34 MB
__device__ float g_scan[BSn * 1024];    // ~34 MB  : residual + h*Cg
__device__ float g_v[BSn * LRn];        // ~17 MB  : normalized gated u
__device__ float g_rin[BSn * Hn];
__device__ float g_cg[BSn * Hn];
__device__ float g_sw[3 * Hn * SHDn * SHDn];  // normalized state_w

// ---------------- helpers ----------------
__device__ __forceinline__ float sigmoidf_(float x) {
    return __fdividef(1.f, 1.f + __expf(-x));
}
__device__ __forceinline__ float tanhf_(float x) {
    float t = __expf(-2.f * fabsf(x));
    float r = __fdividef(1.f - t, 1.f + t);
    return copysignf(r, x);
}
__device__ __forceinline__ float blk_sum256(float v, float* sbuf /*>=8 floats*/) {
    int lane = threadIdx.x & 31, wid = threadIdx.x >> 5;
#pragma unroll
    for (int off = 16; off; off >>= 1) v += __shfl_xor_sync(0xffffffffu, v, off);
    if (lane == 0) sbuf[wid] = v;
    __syncthreads();
    float tot = 0.f;
#pragma unroll
    for (int i = 0; i < 8; i++) tot += sbuf[i];
    __syncthreads();
    return tot;
}
__device__ __forceinline__ void cp_async16(void* smem, const void* gmem) {
    unsigned s = (unsigned)__cvta_generic_to_shared(smem);
    asm volatile("cp.async.cg.shared.global [%0], [%1], 16;\n" ::"r"(s), "l"(gmem));
}

// ---- packed fp32x2 (Blackwell) ----
__device__ __forceinline__ ull ffma2(ull a, ull b, ull c) {
    ull d;
    asm("fma.rn.f32x2 %0, %1, %2, %3;" : "=l"(d) : "l"(a), "l"(b), "l"(c));
    return d;
}
__device__ __forceinline__ ull pk_dup(float x) {   // (x, x)
    ull r;
    asm("mov.b64 %0, {%1, %1};" : "=l"(r) : "f"(x));
    return r;
}
__device__ __forceinline__ ull pk2(float x, float y) {   // (x, y)
    ull r;
    asm("mov.b64 %0, {%1, %2};" : "=l"(r) : "f"(x), "f"(y));
    return r;
}
__device__ __forceinline__ float2 u2f(ull v) {
    float2 f;
    asm("mov.b64 {%0, %1}, %2;" : "=f"(f.x), "=f"(f.y) : "l"(v));
    return f;
}

// ---------------- K1/K6: C[M,N] = A[M,K] @ B[N,K]^T  (fp32, f32x2 inner, db-buffered) ----------------
__global__ __launch_bounds__(256) void sgemm_nt(const float* __restrict__ A,
                                                const float* __restrict__ Bm,
                                                float* __restrict__ C,
                                                int M, int N, int Kd) {
    __shared__ __align__(16) float As[2][8][128];
    __shared__ __align__(16) float Bs[2][8][128];
    int tid = threadIdx.x;
    int m0 = blockIdx.y * 128, n0 = blockIdx.x * 128;
    int tx = tid & 15, ty = tid >> 4;
    int lrow = tid >> 1, lcol = (tid & 1) * 4;

    ull acc[8][4];
#pragma unroll
    for (int i = 0; i < 8; i++)
#pragma unroll
        for (int j = 0; j < 4; j++) acc[i][j] = 0ull;

    const float* Aptr = A + (size_t)(m0 + lrow) * Kd + lcol;
    const float* Bptr = Bm + (size_t)(n0 + lrow) * Kd + lcol;
    bool bvalid = (n0 + lrow) < N;

    // stage 0
    {
        float4 av = *(const float4*)(Aptr);
        float4 bv = bvalid ? *(const float4*)(Bptr) : make_float4(0.f, 0.f, 0.f, 0.f);
        As[0][lcol + 0][lrow] = av.x; As[0][lcol + 1][lrow] = av.y;
        As[0][lcol + 2][lrow] = av.z; As[0][lcol + 3][lrow] = av.w;
        Bs[0][lcol + 0][lrow] = bv.x; Bs[0][lcol + 1][lrow] = bv.y;
        Bs[0][lcol + 2][lrow] = bv.z; Bs[0][lcol + 3][lrow] = bv.w;
    }
    __syncthreads();

    int buf = 0;
    for (int k0 = 0; k0 < Kd; k0 += 8) {
        float4 av_n, bv_n;
        bool has_next = (k0 + 8 < Kd);
        if (has_next) {
            av_n = *(const float4*)(Aptr + k0 + 8);
            bv_n = bvalid ? *(const float4*)(Bptr + k0 + 8) : make_float4(0.f, 0.f, 0.f, 0.f);
        }
#pragma unroll
        for (int kk = 0; kk < 8; kk++) {
            float4 a_lo = *(const float4*)&As[buf][kk][ty * 8];
            float4 a_hi = *(const float4*)&As[buf][kk][ty * 8 + 4];
            ulonglong2 b01 = *(const ulonglong2*)&Bs[buf][kk][tx * 8];
            ulonglong2 b23 = *(const ulonglong2*)&Bs[buf][kk][tx * 8 + 4];
            ull bb[4] = {b01.x, b01.y, b23.x, b23.y};
            float aa[8] = {a_lo.x, a_lo.y, a_lo.z, a_lo.w, a_hi.x, a_hi.y, a_hi.z, a_hi.w};
#pragma unroll
            for (int i = 0; i < 8; i++) {
                ull ad = pk_dup(aa[i]);
#pragma unroll
                for (int j = 0; j < 4; j++) acc[i][j] = ffma2(ad, bb[j], acc[i][j]);
            }
        }
        if (has_next) {
            int nb = buf ^ 1;
            As[nb][lcol + 0][lrow] = av_n.x; As[nb][lcol + 1][lrow] = av_n.y;
            As[nb][lcol + 2][lrow] = av_n.z; As[nb][lcol + 3][lrow] = av_n.w;
            Bs[nb][lcol + 0][lrow] = bv_n.x; Bs[nb][lcol + 1][lrow] = bv_n.y;
            Bs[nb][lcol + 2][lrow] = bv_n.z; Bs[nb][lcol + 3][lrow] = bv_n.w;
            __syncthreads();
            buf = nb;
        }
    }

#pragma unroll
    for (int i = 0; i < 8; i++) {
        int m = m0 + ty * 8 + i;
#pragma unroll
        for (int j = 0; j < 4; j++) {
            float2 c = u2f(acc[i][j]);
            int n = n0 + tx * 8 + 2 * j;
            if (n < N)     C[(size_t)m * N + n] = c.x;
            if (n + 1 < N) C[(size_t)m * N + n + 1] = c.y;
        }
    }
}

// ---------------- K2: causal depthwise conv (K=4) + SiLU ----------------
__global__ __launch_bounds__(256) void conv_silu_kernel(const float* __restrict__ conv_w) {
    int idx = blockIdx.x * blockDim.x + threadIdx.x;   // over BSn*CONVn
    int c = idx % CONVn;
    int row = idx / CONVn;          // b*S + s
    int s = row % Sn;
    float w0 = conv_w[c * 4 + 0], w1 = conv_w[c * 4 + 1];
    float w2 = conv_w[c * 4 + 2], w3 = conv_w[c * 4 + 3];
    float acc = w3 * g_proj[(size_t)row * NPROJ + c];
    if (s >= 1) acc += w2 * g_proj[(size_t)(row - 1) * NPROJ + c];
    if (s >= 2) acc += w1 * g_proj[(size_t)(row - 2) * NPROJ + c];
    if (s >= 3) acc += w0 * g_proj[(size_t)(row - 3) * NPROJ + c];
    g_y[(size_t)row * CONVn + c] = acc * sigmoidf_(acc);   // silu
}

// ---------------- K3b: normalize state_w per head-matrix ----------------
__global__ __launch_bounds__(256) void norm_sw_kernel(const float* __restrict__ sw_in) {
    __shared__ float sbuf[8];
    int m = blockIdx.x;  // 0..23
    const float* src = sw_in + (size_t)m * 16384;
    float ss = 0.f;
    for (int i = threadIdx.x; i < 16384; i += 256) { float v = src[i]; ss += v * v; }
    float tot = blk_sum256(ss, sbuf);
    float inv = 1.f / fmaxf(sqrtf(tot), 1e-12f);
    float* dst = g_sw + (size_t)m * 16384;
    for (int i = threadIdx.x; i < 16384; i += 256) dst[i] = src[i] * inv;
}

// ---------------- K3: norms + expand -> xv, fv, rin, cg ----------------
__global__ __launch_bounds__(256) void build_kernel(const float* __restrict__ w_in_norm,
                                                    const float* __restrict__ w_f_norm,
                                                    const float* __restrict__ w_r_norm) {
    __shared__ float sy[CONVn];
    __shared__ float sb1[8], sb2[8];
    __shared__ float srs[1];
    int row = blockIdx.x;  // b*S + s
    const float* yr = g_y + (size_t)row * CONVn;
    for (int i = threadIdx.x; i < CONVn; i += 256) sy[i] = yr[i];
    __syncthreads();

    float s1 = 0.f, s2 = 0.f;
    for (int i = threadIdx.x; i < 512; i += 256) {
        s1 += sy[i] * sy[i];
        s2 += sy[512 + i] * sy[512 + i];
    }
    float t1 = blk_sum256(s1, sb1);
    float t2 = blk_sum256(s2, sb2);
    if (threadIdx.x == 0) {
        float sr = 0.f;
#pragma unroll
        for (int h = 0; h < 8; h++) sr += sy[1024 + h] * sy[1024 + h];
        srs[0] = rsqrtf(sr * (1.f / 8.f) + 1e-6f);
    }
    float si = rsqrtf(t1 * (1.f / 512.f) + 1e-6f);
    float sf = rsqrtf(t2 * (1.f / 512.f) + 1e-6f);
    __syncthreads();

    float e0 = sy[1040], e1 = sy[1041];
    float* xv = g_xv + (size_t)row * 1024;
    float* fv = g_fv + (size_t)row * 1024;
#pragma unroll
    for (int q = 0; q < 4; q++) {
        int o = threadIdx.x + q * 256;
        int hh = o >> 7, rem = o & 127, ee = rem >> 6, dd = rem & 63;
        int ii = hh * 64 + dd;
        float ex = (ee == 0) ? e0 : e1;
        xv[o] = sy[ii] * si * w_in_norm[ii] * ex;
        fv[o] = sy[512 + ii] * sf * w_f_norm[ii] * ex;
    }
    if (threadIdx.x < 8) {
        g_rin[(size_t)row * 8 + threadIdx.x] = sy[1024 + threadIdx.x] * srs[0] * w_r_norm[threadIdx.x];
        g_cg[(size_t)row * 8 + threadIdx.x] = sy[1032 + threadIdx.x];
    }
}

// ---------------- K4: sequential recurrence, one CTA per (b,h) ----------------
// Thread mapping: e = tid>>1 (state element), half = tid&1 (k-range half).
// Pair (2e, 2e+1) are adjacent lanes -> partial dot products combine via shfl_xor(1).
// Only 2 __syncthreads per step.
__global__ __launch_bounds__(256, 1) void scan_kernel(const float* __restrict__ res_w) {
    int b = blockIdx.x >> 3, hh = blockIdx.x & 7;
    int tid = threadIdx.x;
    int e = tid >> 1, half = tid & 1;

    __shared__ __align__(16) float h_sh[128];
    __shared__ __align__(16) float rh_sh[128];
    __shared__ __align__(16) float xbuf[2][128];
    __shared__ __align__(16) float fbuf[2][128];
    __shared__ float rin_s[Sn], cg_s[Sn];

    // weight columns in packed f32x2 registers over k-pairs of this thread's half
    ull W2[32], F2[32], R2[32];
    {
        const float* bw = g_sw + (size_t)hh * 16384 + half * 64 * 128 + e;
        const float* bf = g_sw + (size_t)(8 + hh) * 16384 + half * 64 * 128 + e;
        const float* br = g_sw + (size_t)(16 + hh) * 16384 + half * 64 * 128 + e;
#pragma unroll
        for (int i = 0; i < 32; i++) {
            W2[i] = pk2(bw[(2 * i) * 128], bw[(2 * i + 1) * 128]);
            F2[i] = pk2(bf[(2 * i) * 128], bf[(2 * i + 1) * 128]);
            R2[i] = pk2(br[(2 * i) * 128], br[(2 * i + 1) * 128]);
        }
    }
    for (int t = tid; t < Sn; t += 256) {
        rin_s[t] = g_rin[(size_t)(b * Sn + t) * 8 + hh];
        cg_s[t]  = g_cg[(size_t)(b * Sn + t) * 8 + hh];
    }
    if (tid < 128) h_sh[tid] = 0.f;
    float resw = res_w[hh];
    size_t rowbase = ((size_t)b * Sn) * 1024 + hh * 128;

    // prefetch t=0
    if (tid < 32)       cp_async16(&xbuf[0][tid * 4], g_xv + rowbase + tid * 4);
    else if (tid < 64)  cp_async16(&fbuf[0][(tid - 32) * 4], g_fv + rowbase + (tid - 32) * 4);
    asm volatile("cp.async.commit_group;");

    const ulonglong2* h4  = (const ulonglong2*)(h_sh)  + half * 8;   // 8 x ulonglong2 = 64 floats
    const ulonglong2* rh4 = (const ulonglong2*)(rh_sh) + half * 8;

    for (int t = 0; t < Sn; t++) {
        int cur = t & 1, nxt = cur ^ 1;
        __syncthreads();   // S1: h_sh from prev step ready; nxt buffers free
        if (t + 1 < Sn) {
            size_t nb = rowbase + (size_t)(t + 1) * 1024;
            if (tid < 32)      cp_async16(&xbuf[nxt][tid * 4], g_xv + nb + tid * 4);
            else if (tid < 64) cp_async16(&fbuf[nxt][(tid - 32) * 4], g_fv + nb + (tid - 32) * 4);
        }
        asm volatile("cp.async.commit_group;");

        // Phase A: pR = h . R[:,e], pF = h . F[:,e] over this thread's k-half
        ull pR2 = 0ull, pF2 = 0ull;
#pragma unroll
        for (int i = 0; i < 8; i++) {
            ulonglong2 hv = h4[i];
            pR2 = ffma2(hv.x, R2[2 * i], pR2);
            pF2 = ffma2(hv.x, F2[2 * i], pF2);
            pR2 = ffma2(hv.y, R2[2 * i + 1], pR2);
            pF2 = ffma2(hv.y, F2[2 * i + 1], pF2);
        }
        float2 fR = u2f(pR2), fF = u2f(pF2);
        float pR = fR.x + fR.y, pF = fF.x + fF.y;
        pR += __shfl_xor_sync(0xffffffffu, pR, 1);
        pF += __shfl_xor_sync(0xffffffffu, pF, 1);

        if (half == 0) {
            float rv = sigmoidf_(rin_s[t] + pR);
            rh_sh[e] = rv * h_sh[e];
        }

        asm volatile("cp.async.wait_group 1;");
        __syncthreads();   // S2: rh_sh ready; cp.async data for t visible to all

        float fgate = 0.f;
        if (half == 1) fgate = sigmoidf_(fbuf[cur][e] + pF);

        // Phase B: pW = (r*h) . W[:,e]
        ull pW2 = 0ull;
#pragma unroll
        for (int i = 0; i < 8; i++) {
            ulonglong2 hv = rh4[i];
            pW2 = ffma2(hv.x, W2[2 * i], pW2);
            pW2 = ffma2(hv.y, W2[2 * i + 1], pW2);
        }
        float2 fW = u2f(pW2);
        float pW = fW.x + fW.y;
        pW += __shfl_xor_sync(0xffffffffu, pW, 1);

        if (half == 1) {
            float xt = xbuf[cur][e];
            float htl = tanhf_(xt + pW);
            float hn = fgate * h_sh[e] + (1.f - fgate) * htl;
            h_sh[e] = hn;
            g_scan[rowbase + (size_t)t * 1024 + e] = resw * xt + hn * cg_s[t];
        }
    }
}

// ---------------- K5: up-proj per head + gate silu + rms -> g_v ----------------
__global__ __launch_bounds__(256) void ugate_kernel(const float* __restrict__ up_w,
                                                    const float* __restrict__ w_g_norm) {
    __shared__ float srow[1024];
    __shared__ float suw[64 * 129];   // padded to kill bank conflicts
    __shared__ float sb[8];
    int row = blockIdx.x;  // b*S + s
    int tid = threadIdx.x;

    const float* sr = g_scan + (size_t)row * 1024;
    for (int i = tid; i < 1024; i += 256) srow[i] = sr[i];
    for (int i = tid; i < 8192; i += 256) {
        int j = i >> 7, d = i & 127;
        suw[j * 129 + d] = up_w[i];
    }
    __syncthreads();

    int o0 = tid * 2, o1 = o0 + 1;
    int hhd = o0 >> 6;            // head (same for o0,o1)
    int j0 = o0 & 63, j1 = o1 & 63;
    const float* a = srow + hhd * 128;
    float acc0 = 0.f, acc1 = 0.f;
#pragma unroll 16
    for (int d = 0; d < 128; d++) {
        float av = a[d];
        acc0 += av * suw[j0 * 129 + d];
        acc1 += av * suw[j1 * 129 + d];
    }
    const float* gptr = g_proj + (size_t)row * NPROJ + CONVn;
    float gA = gptr[o0], gB = gptr[o1];
    float u0 = acc0 * (gA * sigmoidf_(gA));
    float u1 = acc1 * (gB * sigmoidf_(gB));

    float tot = blk_sum256(u0 * u0 + u1 * u1, sb);
    float scale = rsqrtf(tot * (1.f / 512.f) + 1e-6f);
    float* vout = g_v + (size_t)row * 512;
    vout[o0] = u0 * scale * w_g_norm[o0];
    vout[o1] = u1 * scale * w_g_norm[o1];
}

// ---------------- launch ----------------
extern "C" void kernel_launch(void* const* d_in, const int* in_sizes, int n_in,
                              void* d_out, int out_size) {
    const float* x         = (const float*)d_in[0];
    const float* w_in      = (const float*)d_in[1];
    const float* conv_w    = (const float*)d_in[2];
    const float* state_w   = (const float*)d_in[3];
    const float* up_w      = (const float*)d_in[4];
    const float* out_w     = (const float*)d_in[5];
    const float* res_w     = (const float*)d_in[6];
    const float* w_in_norm = (const float*)d_in[7];
    const float* w_f_norm  = (const float*)d_in[8];
    const float* w_r_norm  = (const float*)d_in[9];
    const float* w_g_norm  = (const float*)d_in[10];
    float* out = (float*)d_out;

    float* p_proj = nullptr;
    float* p_v = nullptr;
    cudaGetSymbolAddress((void**)&p_proj, g_proj);
    cudaGetSymbolAddress((void**)&p_v, g_v);

    // K1: proj = x @ w_in^T   [8192,1554,K=1024]
    sgemm_nt<<<dim3((NPROJ + 127) / 128, BSn / 128), 256>>>(x, w_in, p_proj, BSn, NPROJ, Dn);
    // K2: depthwise conv + silu
    conv_silu_kernel<<<(BSn * CONVn) / 256, 256>>>(conv_w);
    // K3b: normalize state_w
    norm_sw_kernel<<<3 * Hn, 256>>>(state_w);
    // K3: norms + expand
    build_kernel<<<BSn, 256>>>(w_in_norm, w_f_norm, w_r_norm);
    // K4: sequential scan, one CTA per (b,h)
    scan_kernel<<<Bn * Hn, 256>>>(res_w);
    // K5: up-proj + gate + rms
    ugate_kernel<<<BSn, 256>>>(up_w, w_g_norm);
    // K6: final = v @ out_w^T  [8192,1024,K=512]
    sgemm_nt<<<dim3(Dn / 128, BSn / 128), 256>>>(p_v, out_w, out, BSn, Dn, LRn);
}

// round 6
// speedup vs baseline: 1.2227x; 1.1650x over previous
#include <cuda_runtime.h>
#include <math.h>

#define Bn    4
#define Sn    2048
#define Dn    1024
#define Hn    8
#define LRn   512
#define LRHn  64
#define SHDn  128
#define EXPn  2
#define Kn    4
#define CONVn 1042
#define NPROJ 1554
#define BSn   8192   // B*S

typedef unsigned long long ull;
typedef unsigned int u32;

// ---------------- scratch (device globals; no runtime allocation) ----------------
__device__ float g_proj[BSn * NPROJ];   // ~51 MB  : x @ w_in^T
__device__ float g_y[BSn * CONVn];      // ~34 MB  : conv+silu output
__device__ float g_xv[BSn * 1024];      // ~34 MB  : [B,S,H,128]
__device__ float g_fv[BSn * 1024];      // ~34 MB
__device__ float g_scan[BSn * 1024];    // ~34 MB  : residual + h*Cg
__device__ float g_v[BSn * LRn];        // ~17 MB  : normalized gated u
__device__ float g_rin[BSn * Hn];
__device__ float g_cg[BSn * Hn];
__device__ float g_sw[3 * Hn * SHDn * SHDn];  // normalized state_w

// ---------------- helpers ----------------
__device__ __forceinline__ float sigmoidf_(float x) {
    return __fdividef(1.f, 1.f + __expf(-x));
}
__device__ __forceinline__ float tanhf_(float x) {
    float t = __expf(-2.f * fabsf(x));
    float r = __fdividef(1.f - t, 1.f + t);
    return copysignf(r, x);
}
__device__ __forceinline__ float blk_sum256(float v, float* sbuf /*>=8 floats*/) {
    int lane = threadIdx.x & 31, wid = threadIdx.x >> 5;
#pragma unroll
    for (int off = 16; off; off >>= 1) v += __shfl_xor_sync(0xffffffffu, v, off);
    if (lane == 0) sbuf[wid] = v;
    __syncthreads();
    float tot = 0.f;
#pragma unroll
    for (int i = 0; i < 8; i++) tot += sbuf[i];
    __syncthreads();
    return tot;
}
__device__ __forceinline__ void cp_async16(void* smem, const void* gmem) {
    unsigned s = (unsigned)__cvta_generic_to_shared(smem);
    asm volatile("cp.async.cg.shared.global [%0], [%1], 16;\n" ::"r"(s), "l"(gmem));
}

// ---- packed fp32x2 (Blackwell baseline) ----
__device__ __forceinline__ ull ffma2(ull a, ull b, ull c) {
    ull d;
    asm("fma.rn.f32x2 %0, %1, %2, %3;" : "=l"(d) : "l"(a), "l"(b), "l"(c));
    return d;
}
__device__ __forceinline__ ull pk2(float x, float y) {
    ull r;
    asm("mov.b64 %0, {%1, %2};" : "=l"(r) : "f"(x), "f"(y));
    return r;
}
__device__ __forceinline__ float2 u2f(ull v) {
    float2 f;
    asm("mov.b64 {%0, %1}, %2;" : "=f"(f.x), "=f"(f.y) : "l"(v));
    return f;
}

// ---- tf32 helpers (sm_80 baseline, no 'a' feature) ----
__device__ __forceinline__ u32 f2tf32(float x) {
    u32 r;
    asm("cvt.rna.tf32.f32 %0, %1;" : "=r"(r) : "f"(x));
    return r;
}
__device__ __forceinline__ void mma_tf32(float* d, const u32* a, const u32* b) {
    asm volatile(
        "mma.sync.aligned.m16n8k8.row.col.f32.tf32.tf32.f32 "
        "{%0,%1,%2,%3}, {%4,%5,%6,%7}, {%8,%9}, {%0,%1,%2,%3};"
        : "+f"(d[0]), "+f"(d[1]), "+f"(d[2]), "+f"(d[3])
        : "r"(a[0]), "r"(a[1]), "r"(a[2]), "r"(a[3]), "r"(b[0]), "r"(b[1]));
}

// ---------------- tensor-core GEMM: C[M,N] = A[M,K] @ B[N,K]^T ----------------
// tf32 hi/lo split (hi = rna-tf32, lo = x-hi), 3 cross products -> ~22 mantissa
// bits (rel err ~2e-7). 128x128 CTA tile, 8 warps (2x4), K-chunks of 32.
#define TCM 128
#define TCN 128
#define TCKC 32
#define WST 36                              // smem row stride in words (conflict-free)
#define TILE_W (128 * WST)                  // words per tile level
#define TC_SMEM_DYN (4 * TILE_W * 4)        // Ahi,Alo,Bhi,Blo = 73728 bytes

__global__ __launch_bounds__(256, 2) void tf32_gemm_nt(const float* __restrict__ A,
                                                       const float* __restrict__ Bm,
                                                       float* __restrict__ C,
                                                       int M, int N, int Kd) {
    extern __shared__ u32 sm[];
    u32* Ahi = sm;
    u32* Alo = sm + TILE_W;
    u32* Bhi = sm + 2 * TILE_W;
    u32* Blo = sm + 3 * TILE_W;

    int tid = threadIdx.x;
    int wid = tid >> 5, lane = tid & 31;
    int g = lane >> 2, t = lane & 3;          // groupID / threadID-in-group
    int wm = (wid >> 2) * 64, wn = (wid & 3) * 32;
    int m0 = blockIdx.y * TCM, n0 = blockIdx.x * TCN;

    float acc[4][4][4];
#pragma unroll
    for (int i = 0; i < 4; i++)
#pragma unroll
        for (int j = 0; j < 4; j++)
#pragma unroll
            for (int q = 0; q < 4; q++) acc[i][j][q] = 0.f;

    for (int k0 = 0; k0 < Kd; k0 += TCKC) {
        // ---- load + split chunk: A[128][32], B[128][32] ----
#pragma unroll
        for (int it = 0; it < 4; it++) {
            int idx = (it * 256 + tid) * 4;      // 0..4095, 4-aligned
            int row = idx >> 5, col = idx & 31;
            float4 av = *(const float4*)(A + (size_t)(m0 + row) * Kd + k0 + col);
            float4 bv = make_float4(0.f, 0.f, 0.f, 0.f);
            if (n0 + row < N)
                bv = *(const float4*)(Bm + (size_t)(n0 + row) * Kd + k0 + col);
            float af[4] = {av.x, av.y, av.z, av.w};
            float bf[4] = {bv.x, bv.y, bv.z, bv.w};
            int base = row * WST + col;
#pragma unroll
            for (int j = 0; j < 4; j++) {
                u32 ah = f2tf32(af[j]);
                u32 al = f2tf32(af[j] - __uint_as_float(ah));
                u32 bh = f2tf32(bf[j]);
                u32 bl = f2tf32(bf[j] - __uint_as_float(bh));
                Ahi[base + j] = ah; Alo[base + j] = al;
                Bhi[base + j] = bh; Blo[base + j] = bl;
            }
        }
        __syncthreads();

        // ---- compute: 4 k8-steps ----
#pragma unroll
        for (int k8 = 0; k8 < 4; k8++) {
            int ko = k8 * 8;
            u32 ah[4][4], al[4][4], bh[4][2], bl[4][2];
#pragma unroll
            for (int mt = 0; mt < 4; mt++) {
                int r0 = (wm + mt * 16 + g) * WST + ko + t;
                int r8 = r0 + 8 * WST;
                ah[mt][0] = Ahi[r0];     ah[mt][1] = Ahi[r8];
                ah[mt][2] = Ahi[r0 + 4]; ah[mt][3] = Ahi[r8 + 4];
                al[mt][0] = Alo[r0];     al[mt][1] = Alo[r8];
                al[mt][2] = Alo[r0 + 4]; al[mt][3] = Alo[r8 + 4];
            }
#pragma unroll
            for (int nt = 0; nt < 4; nt++) {
                int rb = (wn + nt * 8 + g) * WST + ko + t;
                bh[nt][0] = Bhi[rb]; bh[nt][1] = Bhi[rb + 4];
                bl[nt][0] = Blo[rb]; bl[nt][1] = Blo[rb + 4];
            }
#pragma unroll
            for (int mt = 0; mt < 4; mt++)
#pragma unroll
                for (int nt = 0; nt < 4; nt++) {
                    mma_tf32(acc[mt][nt], ah[mt], bh[nt]);   // hi*hi
                    mma_tf32(acc[mt][nt], al[mt], bh[nt]);   // lo*hi
                    mma_tf32(acc[mt][nt], ah[mt], bl[nt]);   // hi*lo
                }
        }
        __syncthreads();
    }

    // ---- epilogue ----
#pragma unroll
    for (int mt = 0; mt < 4; mt++) {
#pragma unroll
        for (int nt = 0; nt < 4; nt++) {
            int r = m0 + wm + mt * 16 + g;
            int c = n0 + wn + nt * 8 + t * 2;
            float* c0 = C + (size_t)r * N + c;
            float* c1 = C + (size_t)(r + 8) * N + c;
            if (c + 1 < N) {
                *(float2*)c0 = make_float2(acc[mt][nt][0], acc[mt][nt][1]);
                *(float2*)c1 = make_float2(acc[mt][nt][2], acc[mt][nt][3]);
            } else if (c < N) {
                *c0 = acc[mt][nt][0];
                *c1 = acc[mt][nt][2];
            }
        }
    }
}

// ---------------- K2: causal depthwise conv (K=4) + SiLU ----------------
__global__ __launch_bounds__(256) void conv_silu_kernel(const float* __restrict__ conv_w) {
    int idx = blockIdx.x * blockDim.x + threadIdx.x;   // over BSn*CONVn
    int c = idx % CONVn;
    int row = idx / CONVn;          // b*S + s
    int s = row % Sn;
    float w0 = conv_w[c * 4 + 0], w1 = conv_w[c * 4 + 1];
    float w2 = conv_w[c * 4 + 2], w3 = conv_w[c * 4 + 3];
    float acc = w3 * g_proj[(size_t)row * NPROJ + c];
    if (s >= 1) acc += w2 * g_proj[(size_t)(row - 1) * NPROJ + c];
    if (s >= 2) acc += w1 * g_proj[(size_t)(row - 2) * NPROJ + c];
    if (s >= 3) acc += w0 * g_proj[(size_t)(row - 3) * NPROJ + c];
    g_y[(size_t)row * CONVn + c] = acc * sigmoidf_(acc);   // silu
}

// ---------------- K3b: normalize state_w per head-matrix ----------------
__global__ __launch_bounds__(256) void norm_sw_kernel(const float* __restrict__ sw_in) {
    __shared__ float sbuf[8];
    int m = blockIdx.x;  // 0..23
    const float* src = sw_in + (size_t)m * 16384;
    float ss = 0.f;
    for (int i = threadIdx.x; i < 16384; i += 256) { float v = src[i]; ss += v * v; }
    float tot = blk_sum256(ss, sbuf);
    float inv = 1.f / fmaxf(sqrtf(tot), 1e-12f);
    float* dst = g_sw + (size_t)m * 16384;
    for (int i = threadIdx.x; i < 16384; i += 256) dst[i] = src[i] * inv;
}

// ---------------- K3: norms + expand -> xv, fv, rin, cg ----------------
__global__ __launch_bounds__(256) void build_kernel(const float* __restrict__ w_in_norm,
                                                    const float* __restrict__ w_f_norm,
                                                    const float* __restrict__ w_r_norm) {
    __shared__ float sy[CONVn];
    __shared__ float sb1[8], sb2[8];
    __shared__ float srs[1];
    int row = blockIdx.x;  // b*S + s
    const float* yr = g_y + (size_t)row * CONVn;
    for (int i = threadIdx.x; i < CONVn; i += 256) sy[i] = yr[i];
    __syncthreads();

    float s1 = 0.f, s2 = 0.f;
    for (int i = threadIdx.x; i < 512; i += 256) {
        s1 += sy[i] * sy[i];
        s2 += sy[512 + i] * sy[512 + i];
    }
    float t1 = blk_sum256(s1, sb1);
    float t2 = blk_sum256(s2, sb2);
    if (threadIdx.x == 0) {
        float sr = 0.f;
#pragma unroll
        for (int h = 0; h < 8; h++) sr += sy[1024 + h] * sy[1024 + h];
        srs[0] = rsqrtf(sr * (1.f / 8.f) + 1e-6f);
    }
    float si = rsqrtf(t1 * (1.f / 512.f) + 1e-6f);
    float sf = rsqrtf(t2 * (1.f / 512.f) + 1e-6f);
    __syncthreads();

    float e0 = sy[1040], e1 = sy[1041];
    float* xv = g_xv + (size_t)row * 1024;
    float* fv = g_fv + (size_t)row * 1024;
#pragma unroll
    for (int q = 0; q < 4; q++) {
        int o = threadIdx.x + q * 256;
        int hh = o >> 7, rem = o & 127, ee = rem >> 6, dd = rem & 63;
        int ii = hh * 64 + dd;
        float ex = (ee == 0) ? e0 : e1;
        xv[o] = sy[ii] * si * w_in_norm[ii] * ex;
        fv[o] = sy[512 + ii] * sf * w_f_norm[ii] * ex;
    }
    if (threadIdx.x < 8) {
        g_rin[(size_t)row * 8 + threadIdx.x] = sy[1024 + threadIdx.x] * srs[0] * w_r_norm[threadIdx.x];
        g_cg[(size_t)row * 8 + threadIdx.x] = sy[1032 + threadIdx.x];
    }
}

// ---------------- K4: sequential recurrence, one CTA per (b,h) ----------------
__global__ __launch_bounds__(256, 1) void scan_kernel(const float* __restrict__ res_w) {
    int b = blockIdx.x >> 3, hh = blockIdx.x & 7;
    int tid = threadIdx.x;
    int e = tid >> 1, half = tid & 1;

    __shared__ __align__(16) float h_sh[128];
    __shared__ __align__(16) float rh_sh[128];
    __shared__ __align__(16) float xbuf[2][128];
    __shared__ __align__(16) float fbuf[2][128];
    __shared__ float rin_s[Sn], cg_s[Sn];

    ull W2[32], F2[32], R2[32];
    {
        const float* bw = g_sw + (size_t)hh * 16384 + half * 64 * 128 + e;
        const float* bf = g_sw + (size_t)(8 + hh) * 16384 + half * 64 * 128 + e;
        const float* br = g_sw + (size_t)(16 + hh) * 16384 + half * 64 * 128 + e;
#pragma unroll
        for (int i = 0; i < 32; i++) {
            W2[i] = pk2(bw[(2 * i) * 128], bw[(2 * i + 1) * 128]);
            F2[i] = pk2(bf[(2 * i) * 128], bf[(2 * i + 1) * 128]);
            R2[i] = pk2(br[(2 * i) * 128], br[(2 * i + 1) * 128]);
        }
    }
    for (int t = tid; t < Sn; t += 256) {
        rin_s[t] = g_rin[(size_t)(b * Sn + t) * 8 + hh];
        cg_s[t]  = g_cg[(size_t)(b * Sn + t) * 8 + hh];
    }
    if (tid < 128) h_sh[tid] = 0.f;
    float resw = res_w[hh];
    size_t rowbase = ((size_t)b * Sn) * 1024 + hh * 128;

    if (tid < 32)       cp_async16(&xbuf[0][tid * 4], g_xv + rowbase + tid * 4);
    else if (tid < 64)  cp_async16(&fbuf[0][(tid - 32) * 4], g_fv + rowbase + (tid - 32) * 4);
    asm volatile("cp.async.commit_group;");

    const ulonglong2* h4  = (const ulonglong2*)(h_sh)  + half * 8;
    const ulonglong2* rh4 = (const ulonglong2*)(rh_sh) + half * 8;

    for (int t = 0; t < Sn; t++) {
        int cur = t & 1, nxt = cur ^ 1;
        __syncthreads();
        if (t + 1 < Sn) {
            size_t nb = rowbase + (size_t)(t + 1) * 1024;
            if (tid < 32)      cp_async16(&xbuf[nxt][tid * 4], g_xv + nb + tid * 4);
            else if (tid < 64) cp_async16(&fbuf[nxt][(tid - 32) * 4], g_fv + nb + (tid - 32) * 4);
        }
        asm volatile("cp.async.commit_group;");

        ull pR2 = 0ull, pF2 = 0ull;
#pragma unroll
        for (int i = 0; i < 8; i++) {
            ulonglong2 hv = h4[i];
            pR2 = ffma2(hv.x, R2[2 * i], pR2);
            pF2 = ffma2(hv.x, F2[2 * i], pF2);
            pR2 = ffma2(hv.y, R2[2 * i + 1], pR2);
            pF2 = ffma2(hv.y, F2[2 * i + 1], pF2);
        }
        float2 fR = u2f(pR2), fF = u2f(pF2);
        float pR = fR.x + fR.y, pF = fF.x + fF.y;
        pR += __shfl_xor_sync(0xffffffffu, pR, 1);
        pF += __shfl_xor_sync(0xffffffffu, pF, 1);

        if (half == 0) {
            float rv = sigmoidf_(rin_s[t] + pR);
            rh_sh[e] = rv * h_sh[e];
        }

        asm volatile("cp.async.wait_group 1;");
        __syncthreads();

        float fgate = 0.f;
        if (half == 1) fgate = sigmoidf_(fbuf[cur][e] + pF);

        ull pW2 = 0ull;
#pragma unroll
        for (int i = 0; i < 8; i++) {
            ulonglong2 hv = rh4[i];
            pW2 = ffma2(hv.x, W2[2 * i], pW2);
            pW2 = ffma2(hv.y, W2[2 * i + 1], pW2);
        }
        float2 fW = u2f(pW2);
        float pW = fW.x + fW.y;
        pW += __shfl_xor_sync(0xffffffffu, pW, 1);

        if (half == 1) {
            float xt = xbuf[cur][e];
            float htl = tanhf_(xt + pW);
            float hn = fgate * h_sh[e] + (1.f - fgate) * htl;
            h_sh[e] = hn;
            g_scan[rowbase + (size_t)t * 1024 + e] = resw * xt + hn * cg_s[t];
        }
    }
}

// ---------------- K5: up-proj per head + gate silu + rms -> g_v ----------------
__global__ __launch_bounds__(256) void ugate_kernel(const float* __restrict__ up_w,
                                                    const float* __restrict__ w_g_norm) {
    __shared__ float srow[1024];
    __shared__ float suw[64 * 129];
    __shared__ float sb[8];
    int row = blockIdx.x;
    int tid = threadIdx.x;

    const float* sr = g_scan + (size_t)row * 1024;
    for (int i = tid; i < 1024; i += 256) srow[i] = sr[i];
    for (int i = tid; i < 8192; i += 256) {
        int j = i >> 7, d = i & 127;
        suw[j * 129 + d] = up_w[i];
    }
    __syncthreads();

    int o0 = tid * 2, o1 = o0 + 1;
    int hhd = o0 >> 6;
    int j0 = o0 & 63, j1 = o1 & 63;
    const float* a = srow + hhd * 128;
    float acc0 = 0.f, acc1 = 0.f;
#pragma unroll 16
    for (int d = 0; d < 128; d++) {
        float av = a[d];
        acc0 += av * suw[j0 * 129 + d];
        acc1 += av * suw[j1 * 129 + d];
    }
    const float* gptr = g_proj + (size_t)row * NPROJ + CONVn;
    float gA = gptr[o0], gB = gptr[o1];
    float u0 = acc0 * (gA * sigmoidf_(gA));
    float u1 = acc1 * (gB * sigmoidf_(gB));

    float tot = blk_sum256(u0 * u0 + u1 * u1, sb);
    float scale = rsqrtf(tot * (1.f / 512.f) + 1e-6f);
    float* vout = g_v + (size_t)row * 512;
    vout[o0] = u0 * scale * w_g_norm[o0];
    vout[o1] = u1 * scale * w_g_norm[o1];
}

// ---------------- launch ----------------
extern "C" void kernel_launch(void* const* d_in, const int* in_sizes, int n_in,
                              void* d_out, int out_size) {
    const float* x         = (const float*)d_in[0];
    const float* w_in      = (const float*)d_in[1];
    const float* conv_w    = (const float*)d_in[2];
    const float* state_w   = (const float*)d_in[3];
    const float* up_w      = (const float*)d_in[4];
    const float* out_w     = (const float*)d_in[5];
    const float* res_w     = (const float*)d_in[6];
    const float* w_in_norm = (const float*)d_in[7];
    const float* w_f_norm  = (const float*)d_in[8];
    const float* w_r_norm  = (const float*)d_in[9];
    const float* w_g_norm  = (const float*)d_in[10];
    float* out = (float*)d_out;

    float* p_proj = nullptr;
    float* p_v = nullptr;
    cudaGetSymbolAddress((void**)&p_proj, g_proj);
    cudaGetSymbolAddress((void**)&p_v, g_v);

    cudaFuncSetAttribute(tf32_gemm_nt, cudaFuncAttributeMaxDynamicSharedMemorySize,
                         TC_SMEM_DYN);

    // K1: proj = x @ w_in^T   [8192,1554,K=1024]
    tf32_gemm_nt<<<dim3((NPROJ + TCN - 1) / TCN, BSn / TCM), 256, TC_SMEM_DYN>>>(
        x, w_in, p_proj, BSn, NPROJ, Dn);
    // K2: depthwise conv + silu
    conv_silu_kernel<<<(BSn * CONVn) / 256, 256>>>(conv_w);
    // K3b: normalize state_w
    norm_sw_kernel<<<3 * Hn, 256>>>(state_w);
    // K3: norms + expand
    build_kernel<<<BSn, 256>>>(w_in_norm, w_f_norm, w_r_norm);
    // K4: sequential scan, one CTA per (b,h)
    scan_kernel<<<Bn * Hn, 256>>>(res_w);
    // K5: up-proj + gate + rms
    ugate_kernel<<<BSn, 256>>>(up_w, w_g_norm);
    // K6: final = v @ out_w^T  [8192,1024,K=512]
    tf32_gemm_nt<<<dim3(Dn / TCN, BSn / TCM), 256, TC_SMEM_DYN>>>(
        p_v, out_w, out, BSn, Dn, LRn);
}

// round 7
// speedup vs baseline: 1.3113x; 1.0725x over previous
#include <cuda_runtime.h>
#include <cuda_fp16.h>
#include <math.h>

#define Bn    4
#define Sn    2048
#define Dn    1024
#define Hn    8
#define LRn   512
#define LRHn  64
#define SHDn  128
#define EXPn  2
#define Kn    4
#define CONVn 1042
#define NPROJ 1554
#define BSn   8192   // B*S

typedef unsigned long long ull;
typedef unsigned int u32;

// ---------------- scratch (device globals; no runtime allocation) ----------------
__device__ float g_proj[BSn * NPROJ];   // ~51 MB  : x @ w_in^T
__device__ float g_y[BSn * CONVn];      // ~34 MB  : conv+silu output
__device__ float g_xv[BSn * 1024];      // ~34 MB  : [B,S,H,128]
__device__ float g_fv[BSn * 1024];      // ~34 MB
__device__ float g_scan[BSn * 1024];    // ~34 MB  : residual + h*Cg
__device__ float g_v[BSn * LRn];        // ~17 MB  : normalized gated u
__device__ float g_rin[BSn * Hn];
__device__ float g_cg[BSn * Hn];
__device__ float g_sw[3 * Hn * SHDn * SHDn];  // normalized state_w

// ---------------- helpers ----------------
__device__ __forceinline__ float sigmoidf_(float x) {
    return __fdividef(1.f, 1.f + __expf(-x));
}
__device__ __forceinline__ float tanhf_(float x) {
    float t = __expf(-2.f * fabsf(x));
    float r = __fdividef(1.f - t, 1.f + t);
    return copysignf(r, x);
}
__device__ __forceinline__ float blk_sum256(float v, float* sbuf /*>=8 floats*/) {
    int lane = threadIdx.x & 31, wid = threadIdx.x >> 5;
#pragma unroll
    for (int off = 16; off; off >>= 1) v += __shfl_xor_sync(0xffffffffu, v, off);
    if (lane == 0) sbuf[wid] = v;
    __syncthreads();
    float tot = 0.f;
#pragma unroll
    for (int i = 0; i < 8; i++) tot += sbuf[i];
    __syncthreads();
    return tot;
}
__device__ __forceinline__ void cp_async16(void* smem, const void* gmem) {
    unsigned s = (unsigned)__cvta_generic_to_shared(smem);
    asm volatile("cp.async.cg.shared.global [%0], [%1], 16;\n" ::"r"(s), "l"(gmem));
}

// ---- packed fp32x2 (Blackwell baseline) ----
__device__ __forceinline__ ull ffma2(ull a, ull b, ull c) {
    ull d;
    asm("fma.rn.f32x2 %0, %1, %2, %3;" : "=l"(d) : "l"(a), "l"(b), "l"(c));
    return d;
}
__device__ __forceinline__ ull pk2(float x, float y) {
    ull r;
    asm("mov.b64 %0, {%1, %2};" : "=l"(r) : "f"(x), "f"(y));
    return r;
}
__device__ __forceinline__ float2 u2f(ull v) {
    float2 f;
    asm("mov.b64 {%0, %1}, %2;" : "=f"(f.x), "=f"(f.y) : "l"(v));
    return f;
}

// ---- fp16 mma (sm_80 baseline, m16n8k16) ----
__device__ __forceinline__ void mma_f16(float* d, const u32* a, const u32* b) {
    asm volatile(
        "mma.sync.aligned.m16n8k16.row.col.f32.f16.f16.f32 "
        "{%0,%1,%2,%3}, {%4,%5,%6,%7}, {%8,%9}, {%0,%1,%2,%3};"
        : "+f"(d[0]), "+f"(d[1]), "+f"(d[2]), "+f"(d[3])
        : "r"(a[0]), "r"(a[1]), "r"(a[2]), "r"(a[3]), "r"(b[0]), "r"(b[1]));
}
__device__ __forceinline__ u32 h2pk(__half x, __half y) {
    __half2 h = __halves2half2(x, y);
    return *(u32*)&h;
}

// ---------------- tensor-core GEMM: C[M,N] = A[M,K] @ B[N,K]^T ----------------
// fp16 hi/lo split: hi = rn(x), lo = rn(x - hi). 3 cross products (hi*hi exact,
// drop lo*lo ~2^-22). 128x128 CTA tile, 8 warps (2x4), K-chunks of 32.
// SMEM per operand row: 16 hi-pairs + 16 lo-pairs (u32) + 4 pad = stride 36
// (fragment loads at (g*36 + t) % 32 = 4g+t -> conflict-free).
#define TCM 128
#define TCN 128
#define TCKC 32
#define WST 36
#define TILE_W (128 * WST)
#define TC_SMEM_DYN (2 * TILE_W * 4)        // 36864 bytes

__global__ __launch_bounds__(256, 2) void h2_gemm_nt(const float* __restrict__ A,
                                                     const float* __restrict__ Bm,
                                                     float* __restrict__ C,
                                                     int M, int N, int Kd) {
    extern __shared__ u32 sm[];
    u32* SA = sm;
    u32* SB = sm + TILE_W;

    int tid = threadIdx.x;
    int wid = tid >> 5, lane = tid & 31;
    int g = lane >> 2, t = lane & 3;
    int wm = (wid >> 2) * 64, wn = (wid & 3) * 32;
    int m0 = blockIdx.y * TCM, n0 = blockIdx.x * TCN;

    float acc[4][4][4];
#pragma unroll
    for (int i = 0; i < 4; i++)
#pragma unroll
        for (int j = 0; j < 4; j++)
#pragma unroll
            for (int q = 0; q < 4; q++) acc[i][j][q] = 0.f;

    for (int k0 = 0; k0 < Kd; k0 += TCKC) {
        // ---- load + split chunk: A[128][32], B[128][32] ----
#pragma unroll
        for (int it = 0; it < 4; it++) {
            int idx = (it * 256 + tid) * 4;      // 0..4095, 4-aligned
            int row = idx >> 5, col = idx & 31;  // col multiple of 4
            float4 av = *(const float4*)(A + (size_t)(m0 + row) * Kd + k0 + col);
            float4 bv = make_float4(0.f, 0.f, 0.f, 0.f);
            if (n0 + row < N)
                bv = *(const float4*)(Bm + (size_t)(n0 + row) * Kd + k0 + col);
            int base = row * WST + (col >> 1);
            // A: hi/lo split
            {
                __half hx = __float2half_rn(av.x), hy = __float2half_rn(av.y);
                __half hz = __float2half_rn(av.z), hw = __float2half_rn(av.w);
                __half lx = __float2half_rn(av.x - __half2float(hx));
                __half ly = __float2half_rn(av.y - __half2float(hy));
                __half lz = __float2half_rn(av.z - __half2float(hz));
                __half lw = __float2half_rn(av.w - __half2float(hw));
                SA[base + 0]  = h2pk(hx, hy);
                SA[base + 1]  = h2pk(hz, hw);
                SA[base + 16] = h2pk(lx, ly);
                SA[base + 17] = h2pk(lz, lw);
            }
            // B: hi/lo split
            {
                __half hx = __float2half_rn(bv.x), hy = __float2half_rn(bv.y);
                __half hz = __float2half_rn(bv.z), hw = __float2half_rn(bv.w);
                __half lx = __float2half_rn(bv.x - __half2float(hx));
                __half ly = __float2half_rn(bv.y - __half2float(hy));
                __half lz = __float2half_rn(bv.z - __half2float(hz));
                __half lw = __float2half_rn(bv.w - __half2float(hw));
                SB[base + 0]  = h2pk(hx, hy);
                SB[base + 1]  = h2pk(hz, hw);
                SB[base + 16] = h2pk(lx, ly);
                SB[base + 17] = h2pk(lz, lw);
            }
        }
        __syncthreads();

        // ---- compute: 2 k16-steps per 32-chunk ----
#pragma unroll
        for (int ks = 0; ks < 2; ks++) {
            int ko = ks * 8;
            u32 bh[4][2], bl[4][2];
#pragma unroll
            for (int nt = 0; nt < 4; nt++) {
                int rb = (wn + nt * 8 + g) * WST + ko + t;
                bh[nt][0] = SB[rb];      bh[nt][1] = SB[rb + 4];
                bl[nt][0] = SB[rb + 16]; bl[nt][1] = SB[rb + 20];
            }
#pragma unroll
            for (int mt = 0; mt < 4; mt++) {
                int r0 = (wm + mt * 16 + g) * WST + ko + t;
                int r8 = r0 + 8 * WST;
                u32 ah[4], al[4];
                ah[0] = SA[r0];      ah[1] = SA[r8];
                ah[2] = SA[r0 + 4];  ah[3] = SA[r8 + 4];
                al[0] = SA[r0 + 16]; al[1] = SA[r8 + 16];
                al[2] = SA[r0 + 20]; al[3] = SA[r8 + 20];
#pragma unroll
                for (int nt = 0; nt < 4; nt++) {
                    mma_f16(acc[mt][nt], ah, bh[nt]);   // hi*hi (exact)
                    mma_f16(acc[mt][nt], ah, bl[nt]);   // hi*lo
                    mma_f16(acc[mt][nt], al, bh[nt]);   // lo*hi
                }
            }
        }
        __syncthreads();
    }

    // ---- epilogue ----
#pragma unroll
    for (int mt = 0; mt < 4; mt++) {
#pragma unroll
        for (int nt = 0; nt < 4; nt++) {
            int r = m0 + wm + mt * 16 + g;
            int c = n0 + wn + nt * 8 + t * 2;
            float* c0 = C + (size_t)r * N + c;
            float* c1 = C + (size_t)(r + 8) * N + c;
            if (c + 1 < N) {
                *(float2*)c0 = make_float2(acc[mt][nt][0], acc[mt][nt][1]);
                *(float2*)c1 = make_float2(acc[mt][nt][2], acc[mt][nt][3]);
            } else if (c < N) {
                *c0 = acc[mt][nt][0];
                *c1 = acc[mt][nt][2];
            }
        }
    }
}

// ---------------- K2: causal depthwise conv (K=4) + SiLU ----------------
__global__ __launch_bounds__(256) void conv_silu_kernel(const float* __restrict__ conv_w) {
    int idx = blockIdx.x * blockDim.x + threadIdx.x;   // over BSn*CONVn
    int c = idx % CONVn;
    int row = idx / CONVn;          // b*S + s
    int s = row % Sn;
    float w0 = conv_w[c * 4 + 0], w1 = conv_w[c * 4 + 1];
    float w2 = conv_w[c * 4 + 2], w3 = conv_w[c * 4 + 3];
    float acc = w3 * g_proj[(size_t)row * NPROJ + c];
    if (s >= 1) acc += w2 * g_proj[(size_t)(row - 1) * NPROJ + c];
    if (s >= 2) acc += w1 * g_proj[(size_t)(row - 2) * NPROJ + c];
    if (s >= 3) acc += w0 * g_proj[(size_t)(row - 3) * NPROJ + c];
    g_y[(size_t)row * CONVn + c] = acc * sigmoidf_(acc);   // silu
}

// ---------------- K3b: normalize state_w per head-matrix ----------------
__global__ __launch_bounds__(256) void norm_sw_kernel(const float* __restrict__ sw_in) {
    __shared__ float sbuf[8];
    int m = blockIdx.x;  // 0..23
    const float* src = sw_in + (size_t)m * 16384;
    float ss = 0.f;
    for (int i = threadIdx.x; i < 16384; i += 256) { float v = src[i]; ss += v * v; }
    float tot = blk_sum256(ss, sbuf);
    float inv = 1.f / fmaxf(sqrtf(tot), 1e-12f);
    float* dst = g_sw + (size_t)m * 16384;
    for (int i = threadIdx.x; i < 16384; i += 256) dst[i] = src[i] * inv;
}

// ---------------- K3: norms + expand -> xv, fv, rin, cg ----------------
__global__ __launch_bounds__(256) void build_kernel(const float* __restrict__ w_in_norm,
                                                    const float* __restrict__ w_f_norm,
                                                    const float* __restrict__ w_r_norm) {
    __shared__ float sy[CONVn];
    __shared__ float sb1[8], sb2[8];
    __shared__ float srs[1];
    int row = blockIdx.x;  // b*S + s
    const float* yr = g_y + (size_t)row * CONVn;
    for (int i = threadIdx.x; i < CONVn; i += 256) sy[i] = yr[i];
    __syncthreads();

    float s1 = 0.f, s2 = 0.f;
    for (int i = threadIdx.x; i < 512; i += 256) {
        s1 += sy[i] * sy[i];
        s2 += sy[512 + i] * sy[512 + i];
    }
    float t1 = blk_sum256(s1, sb1);
    float t2 = blk_sum256(s2, sb2);
    if (threadIdx.x == 0) {
        float sr = 0.f;
#pragma unroll
        for (int h = 0; h < 8; h++) sr += sy[1024 + h] * sy[1024 + h];
        srs[0] = rsqrtf(sr * (1.f / 8.f) + 1e-6f);
    }
    float si = rsqrtf(t1 * (1.f / 512.f) + 1e-6f);
    float sf = rsqrtf(t2 * (1.f / 512.f) + 1e-6f);
    __syncthreads();

    float e0 = sy[1040], e1 = sy[1041];
    float* xv = g_xv + (size_t)row * 1024;
    float* fv = g_fv + (size_t)row * 1024;
#pragma unroll
    for (int q = 0; q < 4; q++) {
        int o = threadIdx.x + q * 256;
        int hh = o >> 7, rem = o & 127, ee = rem >> 6, dd = rem & 63;
        int ii = hh * 64 + dd;
        float ex = (ee == 0) ? e0 : e1;
        xv[o] = sy[ii] * si * w_in_norm[ii] * ex;
        fv[o] = sy[512 + ii] * sf * w_f_norm[ii] * ex;
    }
    if (threadIdx.x < 8) {
        g_rin[(size_t)row * 8 + threadIdx.x] = sy[1024 + threadIdx.x] * srs[0] * w_r_norm[threadIdx.x];
        g_cg[(size_t)row * 8 + threadIdx.x] = sy[1032 + threadIdx.x];
    }
}

// ---------------- K4: sequential recurrence, one CTA per (b,h) ----------------
// e = tid>>1 (state element), half = tid&1 (k-range half); pair combines via
// shfl_xor(1). 2 syncthreads per step. Dual accumulators cut FMA chains in half.
__global__ __launch_bounds__(256, 1) void scan_kernel(const float* __restrict__ res_w) {
    int b = blockIdx.x >> 3, hh = blockIdx.x & 7;
    int tid = threadIdx.x;
    int e = tid >> 1, half = tid & 1;

    __shared__ __align__(16) float h_sh[128];
    __shared__ __align__(16) float rh_sh[128];
    __shared__ __align__(16) float xbuf[2][128];
    __shared__ __align__(16) float fbuf[2][128];
    __shared__ float rin_s[Sn], cg_s[Sn];

    ull W2[32], F2[32], R2[32];
    {
        const float* bw = g_sw + (size_t)hh * 16384 + half * 64 * 128 + e;
        const float* bf = g_sw + (size_t)(8 + hh) * 16384 + half * 64 * 128 + e;
        const float* br = g_sw + (size_t)(16 + hh) * 16384 + half * 64 * 128 + e;
#pragma unroll
        for (int i = 0; i < 32; i++) {
            W2[i] = pk2(bw[(2 * i) * 128], bw[(2 * i + 1) * 128]);
            F2[i] = pk2(bf[(2 * i) * 128], bf[(2 * i + 1) * 128]);
            R2[i] = pk2(br[(2 * i) * 128], br[(2 * i + 1) * 128]);
        }
    }
    for (int t = tid; t < Sn; t += 256) {
        rin_s[t] = g_rin[(size_t)(b * Sn + t) * 8 + hh];
        cg_s[t]  = g_cg[(size_t)(b * Sn + t) * 8 + hh];
    }
    if (tid < 128) h_sh[tid] = 0.f;
    float resw = res_w[hh];
    size_t rowbase = ((size_t)b * Sn) * 1024 + hh * 128;

    if (tid < 32)       cp_async16(&xbuf[0][tid * 4], g_xv + rowbase + tid * 4);
    else if (tid < 64)  cp_async16(&fbuf[0][(tid - 32) * 4], g_fv + rowbase + (tid - 32) * 4);
    asm volatile("cp.async.commit_group;");

    const ulonglong2* h4  = (const ulonglong2*)(h_sh)  + half * 8;
    const ulonglong2* rh4 = (const ulonglong2*)(rh_sh) + half * 8;

    for (int t = 0; t < Sn; t++) {
        int cur = t & 1, nxt = cur ^ 1;
        __syncthreads();
        if (t + 1 < Sn) {
            size_t nb = rowbase + (size_t)(t + 1) * 1024;
            if (tid < 32)      cp_async16(&xbuf[nxt][tid * 4], g_xv + nb + tid * 4);
            else if (tid < 64) cp_async16(&fbuf[nxt][(tid - 32) * 4], g_fv + nb + (tid - 32) * 4);
        }
        asm volatile("cp.async.commit_group;");

        // Phase A: dual accumulators (independent chains)
        ull pRa = 0ull, pRb = 0ull, pFa = 0ull, pFb = 0ull;
#pragma unroll
        for (int i = 0; i < 8; i++) {
            ulonglong2 hv = h4[i];
            pRa = ffma2(hv.x, R2[2 * i], pRa);
            pFa = ffma2(hv.x, F2[2 * i], pFa);
            pRb = ffma2(hv.y, R2[2 * i + 1], pRb);
            pFb = ffma2(hv.y, F2[2 * i + 1], pFb);
        }
        float2 fRa = u2f(pRa), fRb = u2f(pRb), fFa = u2f(pFa), fFb = u2f(pFb);
        float pR = (fRa.x + fRa.y) + (fRb.x + fRb.y);
        float pF = (fFa.x + fFa.y) + (fFb.x + fFb.y);
        pR += __shfl_xor_sync(0xffffffffu, pR, 1);
        pF += __shfl_xor_sync(0xffffffffu, pF, 1);

        if (half == 0) {
            float rv = sigmoidf_(rin_s[t] + pR);
            rh_sh[e] = rv * h_sh[e];
        }

        asm volatile("cp.async.wait_group 1;");
        __syncthreads();

        float fgate = 0.f;
        if (half == 1) fgate = sigmoidf_(fbuf[cur][e] + pF);

        // Phase B: dual accumulators
        ull pWa = 0ull, pWb = 0ull;
#pragma unroll
        for (int i = 0; i < 8; i++) {
            ulonglong2 hv = rh4[i];
            pWa = ffma2(hv.x, W2[2 * i], pWa);
            pWb = ffma2(hv.y, W2[2 * i + 1], pWb);
        }
        float2 fWa = u2f(pWa), fWb = u2f(pWb);
        float pW = (fWa.x + fWa.y) + (fWb.x + fWb.y);
        pW += __shfl_xor_sync(0xffffffffu, pW, 1);

        if (half == 1) {
            float xt = xbuf[cur][e];
            float htl = tanhf_(xt + pW);
            float hn = fgate * h_sh[e] + (1.f - fgate) * htl;
            h_sh[e] = hn;
            g_scan[rowbase + (size_t)t * 1024 + e] = resw * xt + hn * cg_s[t];
        }
    }
}

// ---------------- K5: up-proj per head + gate silu + rms -> g_v ----------------
__global__ __launch_bounds__(256) void ugate_kernel(const float* __restrict__ up_w,
                                                    const float* __restrict__ w_g_norm) {
    __shared__ float srow[1024];
    __shared__ float suw[64 * 129];
    __shared__ float sb[8];
    int row = blockIdx.x;
    int tid = threadIdx.x;

    const float* sr = g_scan + (size_t)row * 1024;
    for (int i = tid; i < 1024; i += 256) srow[i] = sr[i];
    for (int i = tid; i < 8192; i += 256) {
        int j = i >> 7, d = i & 127;
        suw[j * 129 + d] = up_w[i];
    }
    __syncthreads();

    int o0 = tid * 2, o1 = o0 + 1;
    int hhd = o0 >> 6;
    int j0 = o0 & 63, j1 = o1 & 63;
    const float* a = srow + hhd * 128;
    float acc0 = 0.f, acc1 = 0.f;
#pragma unroll 16
    for (int d = 0; d < 128; d++) {
        float av = a[d];
        acc0 += av * suw[j0 * 129 + d];
        acc1 += av * suw[j1 * 129 + d];
    }
    const float* gptr = g_proj + (size_t)row * NPROJ + CONVn;
    float gA = gptr[o0], gB = gptr[o1];
    float u0 = acc0 * (gA * sigmoidf_(gA));
    float u1 = acc1 * (gB * sigmoidf_(gB));

    float tot = blk_sum256(u0 * u0 + u1 * u1, sb);
    float scale = rsqrtf(tot * (1.f / 512.f) + 1e-6f);
    float* vout = g_v + (size_t)row * 512;
    vout[o0] = u0 * scale * w_g_norm[o0];
    vout[o1] = u1 * scale * w_g_norm[o1];
}

// ---------------- launch ----------------
extern "C" void kernel_launch(void* const* d_in, const int* in_sizes, int n_in,
                              void* d_out, int out_size) {
    const float* x         = (const float*)d_in[0];
    const float* w_in      = (const float*)d_in[1];
    const float* conv_w    = (const float*)d_in[2];
    const float* state_w   = (const float*)d_in[3];
    const float* up_w      = (const float*)d_in[4];
    const float* out_w     = (const float*)d_in[5];
    const float* res_w     = (const float*)d_in[6];
    const float* w_in_norm = (const float*)d_in[7];
    const float* w_f_norm  = (const float*)d_in[8];
    const float* w_r_norm  = (const float*)d_in[9];
    const float* w_g_norm  = (const float*)d_in[10];
    float* out = (float*)d_out;

    float* p_proj = nullptr;
    float* p_v = nullptr;
    cudaGetSymbolAddress((void**)&p_proj, g_proj);
    cudaGetSymbolAddress((void**)&p_v, g_v);

    // K1: proj = x @ w_in^T   [8192,1554,K=1024]
    h2_gemm_nt<<<dim3((NPROJ + TCN - 1) / TCN, BSn / TCM), 256, TC_SMEM_DYN>>>(
        x, w_in, p_proj, BSn, NPROJ, Dn);
    // K2: depthwise conv + silu
    conv_silu_kernel<<<(BSn * CONVn) / 256, 256>>>(conv_w);
    // K3b: normalize state_w
    norm_sw_kernel<<<3 * Hn, 256>>>(state_w);
    // K3: norms + expand
    build_kernel<<<BSn, 256>>>(w_in_norm, w_f_norm, w_r_norm);
    // K4: sequential scan, one CTA per (b,h)
    scan_kernel<<<Bn * Hn, 256>>>(res_w);
    // K5: up-proj + gate + rms
    ugate_kernel<<<BSn, 256>>>(up_w, w_g_norm);
    // K6: final = v @ out_w^T  [8192,1024,K=512]
    h2_gemm_nt<<<dim3(Dn / TCN, BSn / TCM), 256, TC_SMEM_DYN>>>(
        p_v, out_w, out, BSn, Dn, LRn);
}